// round 10
// baseline (speedup 1.0000x reference)
#include <cuda_runtime.h>
#include <cuda_fp16.h>
#include <cstdint>

#define NN 100000
#define NE 1200000
#define NF 128
#define NH 64
#define NG 256

#define TILE 512
#define NT ((NN + TILE - 1) / TILE)   // 196 tiles
#define NE4 (NE / 4)                  // 300000

// ---------------- device scratch (no allocations allowed) ----------------
__device__ int    g_cnt[NN];
__device__ float  g_dinv[NN];
__device__ int    g_rowptr[NN + 1];
__device__ int    g_cursor[NN];
__device__ int2   g_csr[NE];          // {src, norm bits}
__device__ unsigned long long g_state[NT];  // decoupled-lookback state
__device__ __half g_h[NN * NH];       // gemm1 output (x @ W1), fp16
__device__ float  g_z[NN];            // per-node scalar z = relu-row . (W2@Wl)
__device__ float  g_w64[NH];          // W2 @ Wl
__device__ float  g_b2wl;             // b2 . Wl
__device__ float  g_pool_s[NG];
__device__ int    g_gcnt[NG];

// ---------------- side stream + events (created once, before harness baseline) ----
struct ForkResources {
    cudaStream_t s2;
    cudaEvent_t evFork, evJoin;
    ForkResources() {
        cudaStreamCreateWithFlags(&s2, cudaStreamNonBlocking);
        cudaEventCreateWithFlags(&evFork, cudaEventDisableTiming);
        cudaEventCreateWithFlags(&evJoin, cudaEventDisableTiming);
    }
};
static ForkResources g_fork;

// ---------------- tf32 mma helpers ----------------
__device__ __forceinline__ unsigned tf32of(float f) {
    unsigned r;
    asm("cvt.rna.tf32.f32 %0, %1;" : "=r"(r) : "f"(f));
    return r;
}
__device__ __forceinline__ void mma_tf32(float* c,
                                         unsigned a0, unsigned a1,
                                         unsigned a2, unsigned a3,
                                         unsigned b0, unsigned b1) {
    asm("mma.sync.aligned.m16n8k8.row.col.f32.tf32.tf32.f32 "
        "{%0,%1,%2,%3}, {%4,%5,%6,%7}, {%8,%9}, {%0,%1,%2,%3};"
        : "+f"(c[0]), "+f"(c[1]), "+f"(c[2]), "+f"(c[3])
        : "r"(a0), "r"(a1), "r"(a2), "r"(a3), "r"(b0), "r"(b1));
}

// ---------------- degree count over dst (int4, 4 edges/thread) ----------------
__global__ void count_k(const int4* __restrict__ dst4) {
    int e = blockIdx.x * blockDim.x + threadIdx.x;
    if (e < NE4) {
        int4 d = __ldg(&dst4[e]);
        atomicAdd(&g_cnt[d.x], 1);
        atomicAdd(&g_cnt[d.y], 1);
        atomicAdd(&g_cnt[d.z], 1);
        atomicAdd(&g_cnt[d.w], 1);
    }
}

// ---------------- w = W2 @ Wl  (64 threads), b2wl ----------------
__global__ void w64_k(const float* __restrict__ W2,
                      const float* __restrict__ b2,
                      const float* __restrict__ Wl) {
    int i = threadIdx.x;
    if (i < NH) {
        float s = 0.f;
#pragma unroll
        for (int j = 0; j < NH; j++) s = fmaf(W2[i * NH + j], Wl[j], s);
        g_w64[i] = s;
    }
    if (i == 0) {
        float s = 0.f;
        for (int j = 0; j < NH; j++) s = fmaf(b2[j], Wl[j], s);
        g_b2wl = s;
    }
}

// ---------------- graph-size histogram (independent; runs on fork branch) ----------
__global__ void gcnt_k(const int* __restrict__ batch) {
    int i = blockIdx.x * blockDim.x + threadIdx.x;
    if (i < NN) atomicAdd(&g_gcnt[batch[i]], 1);
}

// ---------------- single-pass decoupled-lookback scan + dinv ----------------
// replaces tsum/toff/tscan. state word: flag(2 bits)<<62 | value.
// flag: 0 = invalid, 1 = aggregate available, 2 = inclusive prefix available.
__global__ void scan_k() {
    __shared__ int sm[TILE];
    __shared__ int s_prev;
    int t = threadIdx.x;
    int b = blockIdx.x;
    int i = b * TILE + t;

    int c = (i < NN) ? g_cnt[i] : 0;
    if (i < NN) g_dinv[i] = rsqrtf((float)(c + 1));  // +1 self loop
    sm[t] = c;
    __syncthreads();
#pragma unroll
    for (int off = 1; off < TILE; off <<= 1) {
        int u = (t >= off) ? sm[t - off] : 0;
        __syncthreads();
        sm[t] += u;
        __syncthreads();
    }
    int total = sm[TILE - 1];

    if (t == 0) {
        if (b == 0) {
            atomicExch(&g_state[0], (2ull << 62) | (unsigned)total);
            s_prev = 0;
            g_rowptr[NN] = NE;   // sum of degrees is exactly NE
        } else {
            // publish aggregate, then look back
            atomicExch(&g_state[b], (1ull << 62) | (unsigned)total);
            int exc = 0;
            int j = b - 1;
            while (true) {
                unsigned long long v;
                do { v = atomicAdd(&g_state[j], 0ull); } while ((v >> 62) == 0ull);
                exc += (int)(v & 0xFFFFFFFFull);
                if ((v >> 62) == 2ull) break;
                j--;
            }
            atomicExch(&g_state[b], (2ull << 62) | (unsigned)(exc + total));
            s_prev = exc;
        }
    }
    __syncthreads();
    if (i < NN) {
        int pos = s_prev + sm[t] - c;   // global exclusive prefix
        g_rowptr[i] = pos;
        g_cursor[i] = pos;
    }
}

// ---------------- scatter edges into CSR (int4, 4 edges/thread) ----------------
__global__ void scatter_k(const int4* __restrict__ src4,
                          const int4* __restrict__ dst4) {
    int e = blockIdx.x * blockDim.x + threadIdx.x;
    if (e >= NE4) return;
    int4 s = __ldg(&src4[e]);
    int4 d = __ldg(&dst4[e]);
    int p;
    p = atomicAdd(&g_cursor[d.x], 1);
    g_csr[p] = make_int2(s.x, __float_as_int(g_dinv[s.x] * g_dinv[d.x]));
    p = atomicAdd(&g_cursor[d.y], 1);
    g_csr[p] = make_int2(s.y, __float_as_int(g_dinv[s.y] * g_dinv[d.y]));
    p = atomicAdd(&g_cursor[d.z], 1);
    g_csr[p] = make_int2(s.z, __float_as_int(g_dinv[s.z] * g_dinv[d.z]));
    p = atomicAdd(&g_cursor[d.w], 1);
    g_csr[p] = make_int2(s.w, __float_as_int(g_dinv[s.w] * g_dinv[d.w]));
}

// ---------------- TF32 tensor GEMM: g_h[M x 64] = A[M x 128] @ W1[128 x 64], fp16 out ----
__global__ void gemm1_k(const float* __restrict__ A,
                        const float* __restrict__ W, int M) {
    __shared__ unsigned As[128][20];   // tf32 bits, [m][k], pad 4
    __shared__ unsigned Bs[16][68];    // tf32 bits, [k][n], pad 4

    int tid  = threadIdx.x;
    int lane = tid & 31, w = tid >> 5;
    int gid  = lane >> 2, tig = lane & 3;
    int rowBase = blockIdx.x * 128;

    float c[8][4];
#pragma unroll
    for (int nt = 0; nt < 8; nt++)
#pragma unroll
        for (int j = 0; j < 4; j++) c[nt][j] = 0.f;

    for (int k0 = 0; k0 < NF; k0 += 16) {
        {
            int r  = tid >> 1;
            int kq = (tid & 1) * 8;
            int row = rowBase + r;
            float4 a0 = make_float4(0, 0, 0, 0), a1 = a0;
            if (row < M) {
                const float* p = &A[(size_t)row * NF + k0 + kq];
                a0 = *(const float4*)p;
                a1 = *(const float4*)(p + 4);
            }
            As[r][kq + 0] = tf32of(a0.x); As[r][kq + 1] = tf32of(a0.y);
            As[r][kq + 2] = tf32of(a0.z); As[r][kq + 3] = tf32of(a0.w);
            As[r][kq + 4] = tf32of(a1.x); As[r][kq + 5] = tf32of(a1.y);
            As[r][kq + 6] = tf32of(a1.z); As[r][kq + 7] = tf32of(a1.w);
        }
        {
            int kr = tid >> 4;
            int nq = (tid & 15) * 4;
            float4 b = *(const float4*)&W[(size_t)(k0 + kr) * 64 + nq];
            Bs[kr][nq + 0] = tf32of(b.x); Bs[kr][nq + 1] = tf32of(b.y);
            Bs[kr][nq + 2] = tf32of(b.z); Bs[kr][nq + 3] = tf32of(b.w);
        }
        __syncthreads();
#pragma unroll
        for (int ks = 0; ks < 16; ks += 8) {
            unsigned a0 = As[w * 16 + gid    ][ks + tig    ];
            unsigned a1 = As[w * 16 + gid + 8][ks + tig    ];
            unsigned a2 = As[w * 16 + gid    ][ks + tig + 4];
            unsigned a3 = As[w * 16 + gid + 8][ks + tig + 4];
#pragma unroll
            for (int nt = 0; nt < 8; nt++) {
                unsigned b0 = Bs[ks + tig    ][nt * 8 + gid];
                unsigned b1 = Bs[ks + tig + 4][nt * 8 + gid];
                mma_tf32(c[nt], a0, a1, a2, a3, b0, b1);
            }
        }
        __syncthreads();
    }
    int r0 = rowBase + w * 16 + gid;
#pragma unroll
    for (int nt = 0; nt < 8; nt++) {
        int col = nt * 8 + 2 * tig;
        if (r0 < M) {
            __half2 h = __floats2half2_rn(c[nt][0], c[nt][1]);
            *(__half2*)&g_h[(size_t)r0 * 64 + col] = h;
        }
        if (r0 + 8 < M) {
            __half2 h = __floats2half2_rn(c[nt][2], c[nt][3]);
            *(__half2*)&g_h[(size_t)(r0 + 8) * 64 + col] = h;
        }
    }
}

// ---------------- gather1: 16 lanes per node, uint2 (4 halves) per lane ----------------
__global__ void gather1_k(const float* __restrict__ bias) {
    int node = (blockIdx.x * blockDim.x + threadIdx.x) >> 4;
    if (node >= NN) return;
    int g = threadIdx.x & 15;   // lane within 16-lane group; cols 4g..4g+3

    int beg = g_rowptr[node];
    int end = g_rowptr[node + 1];
    const uint2* __restrict__ h4 = (const uint2*)g_h;  // 4 halves per uint2

    float4 acc = make_float4(0.f, 0.f, 0.f, 0.f);
    int j = beg;
    for (; j + 2 <= end; j += 2) {
        int2 e0 = __ldg(&g_csr[j]);
        int2 e1 = __ldg(&g_csr[j + 1]);
        uint2 r0 = __ldg(&h4[(size_t)e0.x * 16 + g]);
        uint2 r1 = __ldg(&h4[(size_t)e1.x * 16 + g]);
        float n0 = __int_as_float(e0.y), n1 = __int_as_float(e1.y);
        float2 p0 = __half22float2(*(__half2*)&r0.x);
        float2 q0 = __half22float2(*(__half2*)&r0.y);
        float2 p1 = __half22float2(*(__half2*)&r1.x);
        float2 q1 = __half22float2(*(__half2*)&r1.y);
        acc.x = fmaf(n0, p0.x, acc.x); acc.y = fmaf(n0, p0.y, acc.y);
        acc.z = fmaf(n0, q0.x, acc.z); acc.w = fmaf(n0, q0.y, acc.w);
        acc.x = fmaf(n1, p1.x, acc.x); acc.y = fmaf(n1, p1.y, acc.y);
        acc.z = fmaf(n1, q1.x, acc.z); acc.w = fmaf(n1, q1.y, acc.w);
    }
    if (j < end) {
        int2 e = __ldg(&g_csr[j]);
        uint2 r = __ldg(&h4[(size_t)e.x * 16 + g]);
        float n = __int_as_float(e.y);
        float2 p = __half22float2(*(__half2*)&r.x);
        float2 q = __half22float2(*(__half2*)&r.y);
        acc.x = fmaf(n, p.x, acc.x); acc.y = fmaf(n, p.y, acc.y);
        acc.z = fmaf(n, q.x, acc.z); acc.w = fmaf(n, q.y, acc.w);
    }
    float di = g_dinv[node];
    float sn = di * di;
    uint2 rs = h4[(size_t)node * 16 + g];
    float2 ps = __half22float2(*(__half2*)&rs.x);
    float2 qs = __half22float2(*(__half2*)&rs.y);
    float4 bi = *(const float4*)&bias[4 * g];
    acc.x = fmaxf(fmaf(sn, ps.x, acc.x) + bi.x, 0.f);
    acc.y = fmaxf(fmaf(sn, ps.y, acc.y) + bi.y, 0.f);
    acc.z = fmaxf(fmaf(sn, qs.x, acc.z) + bi.z, 0.f);
    acc.w = fmaxf(fmaf(sn, qs.y, acc.w) + bi.w, 0.f);

    float4 wv = *(const float4*)&g_w64[4 * g];
    float v = acc.x * wv.x + acc.y * wv.y + acc.z * wv.z + acc.w * wv.w;
#pragma unroll
    for (int o = 8; o; o >>= 1) v += __shfl_xor_sync(0xffffffffu, v, o);
    if (g == 0) g_z[node] = v;
}

// ---------------- gather2: thread per node, scalar agg + pool (4x unroll) ----------------
__global__ void gather2_k(const int* __restrict__ batch) {
    int node = blockIdx.x * blockDim.x + threadIdx.x;
    if (node >= NN) return;
    int beg = g_rowptr[node];
    int end = g_rowptr[node + 1];
    float s = 0.f;
    int j = beg;
    for (; j + 4 <= end; j += 4) {
        int2 e0 = __ldg(&g_csr[j]);
        int2 e1 = __ldg(&g_csr[j + 1]);
        int2 e2 = __ldg(&g_csr[j + 2]);
        int2 e3 = __ldg(&g_csr[j + 3]);
        float z0 = __ldg(&g_z[e0.x]);
        float z1 = __ldg(&g_z[e1.x]);
        float z2 = __ldg(&g_z[e2.x]);
        float z3 = __ldg(&g_z[e3.x]);
        s = fmaf(__int_as_float(e0.y), z0, s);
        s = fmaf(__int_as_float(e1.y), z1, s);
        s = fmaf(__int_as_float(e2.y), z2, s);
        s = fmaf(__int_as_float(e3.y), z3, s);
    }
    for (; j < end; j++) {
        int2 e = __ldg(&g_csr[j]);
        s = fmaf(__int_as_float(e.y), __ldg(&g_z[e.x]), s);
    }
    float di = g_dinv[node];
    s = fmaf(di * di, g_z[node], s);
    atomicAdd(&g_pool_s[batch[node]], s);
}

// ---------------- final ----------------
__global__ void final_k(const float* __restrict__ bl, float* __restrict__ out) {
    int g = blockIdx.x * blockDim.x + threadIdx.x;
    if (g >= NG) return;
    float c = (float)g_gcnt[g];
    out[g] = g_pool_s[g] / fmaxf(c, 1.f) + g_b2wl + bl[0];
}

// ---------------- launch ----------------
extern "C" void kernel_launch(void* const* d_in, const int* in_sizes, int n_in,
                              void* d_out, int out_size) {
    const float* x     = (const float*)d_in[0];
    const int*   ei    = (const int*)d_in[1];    // int32 (JAX x64 disabled)
    const int*   batch = (const int*)d_in[2];
    const float* W1    = (const float*)d_in[3];
    const float* b1    = (const float*)d_in[4];
    const float* W2    = (const float*)d_in[5];
    const float* b2    = (const float*)d_in[6];
    const float* Wl    = (const float*)d_in[7];
    const float* bl    = (const float*)d_in[8];
    float* out = (float*)d_out;

    const int4* src4 = (const int4*)ei;
    const int4* dst4 = (const int4*)(ei + NE);

    // zero-init via memset nodes (DMA, cheap)
    void *pCnt, *pPool, *pGcnt, *pState;
    cudaGetSymbolAddress(&pCnt, g_cnt);
    cudaGetSymbolAddress(&pPool, g_pool_s);
    cudaGetSymbolAddress(&pGcnt, g_gcnt);
    cudaGetSymbolAddress(&pState, g_state);
    cudaMemsetAsync(pCnt, 0, NN * sizeof(int), 0);
    cudaMemsetAsync(pPool, 0, NG * sizeof(float), 0);
    cudaMemsetAsync(pGcnt, 0, NG * sizeof(int), 0);
    cudaMemsetAsync(pState, 0, NT * sizeof(unsigned long long), 0);

    // ---- fork: GEMM + graph-size branch on side stream ----
    cudaEventRecord(g_fork.evFork, 0);
    cudaStreamWaitEvent(g_fork.s2, g_fork.evFork, 0);
    gemm1_k<<<(NN + 127) / 128, 256, 0, g_fork.s2>>>(x, W1, NN);
    w64_k  <<<1, 64, 0, g_fork.s2>>>(W2, b2, Wl);
    gcnt_k <<<(NN + 255) / 256, 256, 0, g_fork.s2>>>(batch);
    cudaEventRecord(g_fork.evJoin, g_fork.s2);

    // ---- main chain: CSR build on capture stream ----
    count_k  <<<(NE4 + 255) / 256, 256>>>(dst4);
    scan_k   <<<NT, TILE>>>();
    scatter_k<<<(NE4 + 255) / 256, 256>>>(src4, dst4);

    // ---- join: gathers need both CSR and g_h ----
    cudaStreamWaitEvent(0, g_fork.evJoin, 0);
    gather1_k<<<(NN * 16 + 255) / 256, 256>>>(b1);
    gather2_k<<<(NN + 255) / 256, 256>>>(batch);
    final_k  <<<1, NG>>>(bl, out);
}

// round 11
// speedup vs baseline: 1.0211x; 1.0211x over previous
#include <cuda_runtime.h>
#include <cuda_fp16.h>
#include <cstdint>

#define NN 100000
#define NE 1200000
#define NF 128
#define NH 64
#define NG 256

#define TILE 512
#define NT ((NN + TILE - 1) / TILE)   // 196 tiles
#define NE4 (NE / 4)                  // 300000

// ---------------- device scratch (no allocations allowed) ----------------
__device__ int    g_cnt[NN];
__device__ float  g_dinv[NN];
__device__ int    g_rowptr[NN + 1];
__device__ int    g_cursor[NN];
__device__ int2   g_csr[NE];          // {src, norm bits}
__device__ unsigned long long g_state[NT];  // decoupled-lookback state
__device__ __half g_h[NN * NH];       // gemm1 output (x @ W1), fp16
__device__ float  g_z[NN];            // per-node scalar z = relu-row . (W2@Wl)
__device__ float  g_w64[NH];          // W2 @ Wl
__device__ float  g_b2wl;             // b2 . Wl
__device__ float  g_pool_s[NG];
__device__ int    g_gcnt[NG];

// ---------------- side stream + events (created once, before harness baseline) ----
struct ForkResources {
    cudaStream_t s2;
    cudaEvent_t evFork, evJoin;
    ForkResources() {
        cudaStreamCreateWithFlags(&s2, cudaStreamNonBlocking);
        cudaEventCreateWithFlags(&evFork, cudaEventDisableTiming);
        cudaEventCreateWithFlags(&evJoin, cudaEventDisableTiming);
    }
};
static ForkResources g_fork;

// ---------------- tf32 mma helpers ----------------
__device__ __forceinline__ unsigned tf32of(float f) {
    unsigned r;
    asm("cvt.rna.tf32.f32 %0, %1;" : "=r"(r) : "f"(f));
    return r;
}
__device__ __forceinline__ void mma_tf32(float* c,
                                         unsigned a0, unsigned a1,
                                         unsigned a2, unsigned a3,
                                         unsigned b0, unsigned b1) {
    asm("mma.sync.aligned.m16n8k8.row.col.f32.tf32.tf32.f32 "
        "{%0,%1,%2,%3}, {%4,%5,%6,%7}, {%8,%9}, {%0,%1,%2,%3};"
        : "+f"(c[0]), "+f"(c[1]), "+f"(c[2]), "+f"(c[3])
        : "r"(a0), "r"(a1), "r"(a2), "r"(a3), "r"(b0), "r"(b1));
}

// ---------------- degree count over dst (int4, 4 edges/thread) ----------------
__global__ void count_k(const int4* __restrict__ dst4) {
    int e = blockIdx.x * blockDim.x + threadIdx.x;
    if (e < NE4) {
        int4 d = __ldg(&dst4[e]);
        atomicAdd(&g_cnt[d.x], 1);
        atomicAdd(&g_cnt[d.y], 1);
        atomicAdd(&g_cnt[d.z], 1);
        atomicAdd(&g_cnt[d.w], 1);
    }
}

// ---------------- w = W2 @ Wl  (64 threads), b2wl ----------------
__global__ void w64_k(const float* __restrict__ W2,
                      const float* __restrict__ b2,
                      const float* __restrict__ Wl) {
    int i = threadIdx.x;
    if (i < NH) {
        float s = 0.f;
#pragma unroll
        for (int j = 0; j < NH; j++) s = fmaf(W2[i * NH + j], Wl[j], s);
        g_w64[i] = s;
    }
    if (i == 0) {
        float s = 0.f;
        for (int j = 0; j < NH; j++) s = fmaf(b2[j], Wl[j], s);
        g_b2wl = s;
    }
}

// ---------------- graph-size histogram (independent; runs on fork branch) ----------
__global__ void gcnt_k(const int* __restrict__ batch) {
    int i = blockIdx.x * blockDim.x + threadIdx.x;
    if (i < NN) atomicAdd(&g_gcnt[batch[i]], 1);
}

// ---------------- single-pass scan + dinv, WARP-PARALLEL lookback ----------------
// state word: flag(2 bits)<<62 | value. 0=invalid, 1=aggregate, 2=inclusive prefix.
__global__ void scan_k() {
    __shared__ int sm[TILE];
    __shared__ int s_prev;
    int t = threadIdx.x;
    int b = blockIdx.x;
    int i = b * TILE + t;

    int c = (i < NN) ? g_cnt[i] : 0;
    if (i < NN) g_dinv[i] = rsqrtf((float)(c + 1));  // +1 self loop
    sm[t] = c;
    __syncthreads();
#pragma unroll
    for (int off = 1; off < TILE; off <<= 1) {
        int u = (t >= off) ? sm[t - off] : 0;
        __syncthreads();
        sm[t] += u;
        __syncthreads();
    }
    int total = sm[TILE - 1];

    if (b == 0) {
        if (t == 0) {
            atomicExch(&g_state[0], (2ull << 62) | (unsigned)total);
            s_prev = 0;
            g_rowptr[NN] = NE;   // sum of degrees is exactly NE
        }
    } else if (t < 32) {
        if (t == 0) atomicExch(&g_state[b], (1ull << 62) | (unsigned)total);
        __syncwarp();
        int exc = 0;
        int wend = b;             // window covers [wend-32, wend)
        while (true) {
            int j = wend - 32 + t;
            unsigned long long v;
            unsigned flag;
            do {
                v = (j >= 0) ? atomicAdd(&g_state[j], 0ull) : (2ull << 62);
                flag = (unsigned)(v >> 62);
            } while (__any_sync(0xffffffffu, flag == 0u));
            unsigned pmask = __ballot_sync(0xffffffffu, flag == 2u);
            int val = (int)(v & 0xFFFFFFFFull);
            if (pmask) {
                int hi = 31 - __clz(pmask);   // highest flag-2 lane
                int contrib = (t >= hi) ? val : 0;  // prefix@hi + aggregates above
#pragma unroll
                for (int o = 16; o; o >>= 1)
                    contrib += __shfl_xor_sync(0xffffffffu, contrib, o);
                exc += contrib;
                break;
            } else {
                int contrib = val;                  // all aggregates
#pragma unroll
                for (int o = 16; o; o >>= 1)
                    contrib += __shfl_xor_sync(0xffffffffu, contrib, o);
                exc += contrib;
                wend -= 32;
            }
        }
        if (t == 0) {
            atomicExch(&g_state[b], (2ull << 62) | (unsigned)(exc + total));
            s_prev = exc;
        }
    }
    __syncthreads();
    if (i < NN) {
        int pos = s_prev + sm[t] - c;   // global exclusive prefix
        g_rowptr[i] = pos;
        g_cursor[i] = pos;
    }
}

// ---------------- scatter edges into CSR (int4, 4 edges/thread) ----------------
__global__ void scatter_k(const int4* __restrict__ src4,
                          const int4* __restrict__ dst4) {
    int e = blockIdx.x * blockDim.x + threadIdx.x;
    if (e >= NE4) return;
    int4 s = __ldg(&src4[e]);
    int4 d = __ldg(&dst4[e]);
    int p;
    p = atomicAdd(&g_cursor[d.x], 1);
    g_csr[p] = make_int2(s.x, __float_as_int(g_dinv[s.x] * g_dinv[d.x]));
    p = atomicAdd(&g_cursor[d.y], 1);
    g_csr[p] = make_int2(s.y, __float_as_int(g_dinv[s.y] * g_dinv[d.y]));
    p = atomicAdd(&g_cursor[d.z], 1);
    g_csr[p] = make_int2(s.z, __float_as_int(g_dinv[s.z] * g_dinv[d.z]));
    p = atomicAdd(&g_cursor[d.w], 1);
    g_csr[p] = make_int2(s.w, __float_as_int(g_dinv[s.w] * g_dinv[d.w]));
}

// ---------------- TF32 tensor GEMM: g_h[M x 64] = A[M x 128] @ W1[128 x 64], fp16 out ----
__global__ void gemm1_k(const float* __restrict__ A,
                        const float* __restrict__ W, int M) {
    __shared__ unsigned As[128][20];   // tf32 bits, [m][k], pad 4
    __shared__ unsigned Bs[16][68];    // tf32 bits, [k][n], pad 4

    int tid  = threadIdx.x;
    int lane = tid & 31, w = tid >> 5;
    int gid  = lane >> 2, tig = lane & 3;
    int rowBase = blockIdx.x * 128;

    float c[8][4];
#pragma unroll
    for (int nt = 0; nt < 8; nt++)
#pragma unroll
        for (int j = 0; j < 4; j++) c[nt][j] = 0.f;

    for (int k0 = 0; k0 < NF; k0 += 16) {
        {
            int r  = tid >> 1;
            int kq = (tid & 1) * 8;
            int row = rowBase + r;
            float4 a0 = make_float4(0, 0, 0, 0), a1 = a0;
            if (row < M) {
                const float* p = &A[(size_t)row * NF + k0 + kq];
                a0 = *(const float4*)p;
                a1 = *(const float4*)(p + 4);
            }
            As[r][kq + 0] = tf32of(a0.x); As[r][kq + 1] = tf32of(a0.y);
            As[r][kq + 2] = tf32of(a0.z); As[r][kq + 3] = tf32of(a0.w);
            As[r][kq + 4] = tf32of(a1.x); As[r][kq + 5] = tf32of(a1.y);
            As[r][kq + 6] = tf32of(a1.z); As[r][kq + 7] = tf32of(a1.w);
        }
        {
            int kr = tid >> 4;
            int nq = (tid & 15) * 4;
            float4 b = *(const float4*)&W[(size_t)(k0 + kr) * 64 + nq];
            Bs[kr][nq + 0] = tf32of(b.x); Bs[kr][nq + 1] = tf32of(b.y);
            Bs[kr][nq + 2] = tf32of(b.z); Bs[kr][nq + 3] = tf32of(b.w);
        }
        __syncthreads();
#pragma unroll
        for (int ks = 0; ks < 16; ks += 8) {
            unsigned a0 = As[w * 16 + gid    ][ks + tig    ];
            unsigned a1 = As[w * 16 + gid + 8][ks + tig    ];
            unsigned a2 = As[w * 16 + gid    ][ks + tig + 4];
            unsigned a3 = As[w * 16 + gid + 8][ks + tig + 4];
#pragma unroll
            for (int nt = 0; nt < 8; nt++) {
                unsigned b0 = Bs[ks + tig    ][nt * 8 + gid];
                unsigned b1 = Bs[ks + tig + 4][nt * 8 + gid];
                mma_tf32(c[nt], a0, a1, a2, a3, b0, b1);
            }
        }
        __syncthreads();
    }
    int r0 = rowBase + w * 16 + gid;
#pragma unroll
    for (int nt = 0; nt < 8; nt++) {
        int col = nt * 8 + 2 * tig;
        if (r0 < M) {
            __half2 h = __floats2half2_rn(c[nt][0], c[nt][1]);
            *(__half2*)&g_h[(size_t)r0 * 64 + col] = h;
        }
        if (r0 + 8 < M) {
            __half2 h = __floats2half2_rn(c[nt][2], c[nt][3]);
            *(__half2*)&g_h[(size_t)(r0 + 8) * 64 + col] = h;
        }
    }
}

// ---------------- gather1: 16 lanes per node, uint2 (4 halves) per lane ----------------
__global__ void gather1_k(const float* __restrict__ bias) {
    int node = (blockIdx.x * blockDim.x + threadIdx.x) >> 4;
    if (node >= NN) return;
    int g = threadIdx.x & 15;   // lane within 16-lane group; cols 4g..4g+3

    int beg = g_rowptr[node];
    int end = g_rowptr[node + 1];
    const uint2* __restrict__ h4 = (const uint2*)g_h;  // 4 halves per uint2

    float4 acc = make_float4(0.f, 0.f, 0.f, 0.f);
    int j = beg;
    for (; j + 2 <= end; j += 2) {
        int2 e0 = __ldg(&g_csr[j]);
        int2 e1 = __ldg(&g_csr[j + 1]);
        uint2 r0 = __ldg(&h4[(size_t)e0.x * 16 + g]);
        uint2 r1 = __ldg(&h4[(size_t)e1.x * 16 + g]);
        float n0 = __int_as_float(e0.y), n1 = __int_as_float(e1.y);
        float2 p0 = __half22float2(*(__half2*)&r0.x);
        float2 q0 = __half22float2(*(__half2*)&r0.y);
        float2 p1 = __half22float2(*(__half2*)&r1.x);
        float2 q1 = __half22float2(*(__half2*)&r1.y);
        acc.x = fmaf(n0, p0.x, acc.x); acc.y = fmaf(n0, p0.y, acc.y);
        acc.z = fmaf(n0, q0.x, acc.z); acc.w = fmaf(n0, q0.y, acc.w);
        acc.x = fmaf(n1, p1.x, acc.x); acc.y = fmaf(n1, p1.y, acc.y);
        acc.z = fmaf(n1, q1.x, acc.z); acc.w = fmaf(n1, q1.y, acc.w);
    }
    if (j < end) {
        int2 e = __ldg(&g_csr[j]);
        uint2 r = __ldg(&h4[(size_t)e.x * 16 + g]);
        float n = __int_as_float(e.y);
        float2 p = __half22float2(*(__half2*)&r.x);
        float2 q = __half22float2(*(__half2*)&r.y);
        acc.x = fmaf(n, p.x, acc.x); acc.y = fmaf(n, p.y, acc.y);
        acc.z = fmaf(n, q.x, acc.z); acc.w = fmaf(n, q.y, acc.w);
    }
    float di = g_dinv[node];
    float sn = di * di;
    uint2 rs = h4[(size_t)node * 16 + g];
    float2 ps = __half22float2(*(__half2*)&rs.x);
    float2 qs = __half22float2(*(__half2*)&rs.y);
    float4 bi = *(const float4*)&bias[4 * g];
    acc.x = fmaxf(fmaf(sn, ps.x, acc.x) + bi.x, 0.f);
    acc.y = fmaxf(fmaf(sn, ps.y, acc.y) + bi.y, 0.f);
    acc.z = fmaxf(fmaf(sn, qs.x, acc.z) + bi.z, 0.f);
    acc.w = fmaxf(fmaf(sn, qs.y, acc.w) + bi.w, 0.f);

    float4 wv = *(const float4*)&g_w64[4 * g];
    float v = acc.x * wv.x + acc.y * wv.y + acc.z * wv.z + acc.w * wv.w;
#pragma unroll
    for (int o = 8; o; o >>= 1) v += __shfl_xor_sync(0xffffffffu, v, o);
    if (g == 0) g_z[node] = v;
}

// ---------------- gather2: thread per node, scalar agg + pool (4x unroll) ----------------
__global__ void gather2_k(const int* __restrict__ batch) {
    int node = blockIdx.x * blockDim.x + threadIdx.x;
    if (node >= NN) return;
    int beg = g_rowptr[node];
    int end = g_rowptr[node + 1];
    float s = 0.f;
    int j = beg;
    for (; j + 4 <= end; j += 4) {
        int2 e0 = __ldg(&g_csr[j]);
        int2 e1 = __ldg(&g_csr[j + 1]);
        int2 e2 = __ldg(&g_csr[j + 2]);
        int2 e3 = __ldg(&g_csr[j + 3]);
        float z0 = __ldg(&g_z[e0.x]);
        float z1 = __ldg(&g_z[e1.x]);
        float z2 = __ldg(&g_z[e2.x]);
        float z3 = __ldg(&g_z[e3.x]);
        s = fmaf(__int_as_float(e0.y), z0, s);
        s = fmaf(__int_as_float(e1.y), z1, s);
        s = fmaf(__int_as_float(e2.y), z2, s);
        s = fmaf(__int_as_float(e3.y), z3, s);
    }
    for (; j < end; j++) {
        int2 e = __ldg(&g_csr[j]);
        s = fmaf(__int_as_float(e.y), __ldg(&g_z[e.x]), s);
    }
    float di = g_dinv[node];
    s = fmaf(di * di, g_z[node], s);
    atomicAdd(&g_pool_s[batch[node]], s);
}

// ---------------- final ----------------
__global__ void final_k(const float* __restrict__ bl, float* __restrict__ out) {
    int g = blockIdx.x * blockDim.x + threadIdx.x;
    if (g >= NG) return;
    float c = (float)g_gcnt[g];
    out[g] = g_pool_s[g] / fmaxf(c, 1.f) + g_b2wl + bl[0];
}

// ---------------- launch ----------------
extern "C" void kernel_launch(void* const* d_in, const int* in_sizes, int n_in,
                              void* d_out, int out_size) {
    const float* x     = (const float*)d_in[0];
    const int*   ei    = (const int*)d_in[1];    // int32 (JAX x64 disabled)
    const int*   batch = (const int*)d_in[2];
    const float* W1    = (const float*)d_in[3];
    const float* b1    = (const float*)d_in[4];
    const float* W2    = (const float*)d_in[5];
    const float* b2    = (const float*)d_in[6];
    const float* Wl    = (const float*)d_in[7];
    const float* bl    = (const float*)d_in[8];
    float* out = (float*)d_out;

    const int4* src4 = (const int4*)ei;
    const int4* dst4 = (const int4*)(ei + NE);

    // zero-init via memset nodes (DMA, cheap)
    void *pCnt, *pPool, *pGcnt, *pState;
    cudaGetSymbolAddress(&pCnt, g_cnt);
    cudaGetSymbolAddress(&pPool, g_pool_s);
    cudaGetSymbolAddress(&pGcnt, g_gcnt);
    cudaGetSymbolAddress(&pState, g_state);
    cudaMemsetAsync(pCnt, 0, NN * sizeof(int), 0);
    cudaMemsetAsync(pPool, 0, NG * sizeof(float), 0);
    cudaMemsetAsync(pGcnt, 0, NG * sizeof(int), 0);
    cudaMemsetAsync(pState, 0, NT * sizeof(unsigned long long), 0);

    // ---- fork: GEMM + graph-size branch on side stream ----
    cudaEventRecord(g_fork.evFork, 0);
    cudaStreamWaitEvent(g_fork.s2, g_fork.evFork, 0);
    gemm1_k<<<(NN + 127) / 128, 256, 0, g_fork.s2>>>(x, W1, NN);
    w64_k  <<<1, 64, 0, g_fork.s2>>>(W2, b2, Wl);
    gcnt_k <<<(NN + 255) / 256, 256, 0, g_fork.s2>>>(batch);
    cudaEventRecord(g_fork.evJoin, g_fork.s2);

    // ---- main chain: CSR build on capture stream ----
    count_k  <<<(NE4 + 255) / 256, 256>>>(dst4);
    scan_k   <<<NT, TILE>>>();
    scatter_k<<<(NE4 + 255) / 256, 256>>>(src4, dst4);

    // ---- join: gathers need both CSR and g_h ----
    cudaStreamWaitEvent(0, g_fork.evJoin, 0);
    gather1_k<<<(NN * 16 + 255) / 256, 256>>>(b1);
    gather2_k<<<(NN + 255) / 256, 256>>>(batch);
    final_k  <<<1, NG>>>(bl, out);
}

// round 12
// speedup vs baseline: 1.2148x; 1.1897x over previous
#include <cuda_runtime.h>
#include <cuda_fp16.h>
#include <cstdint>

#define NN 100000
#define NE 1200000
#define NF 128
#define NH 64
#define NG 256

#define TILE 512
#define NT ((NN + TILE - 1) / TILE)   // 196 tiles
#define NE4 (NE / 4)                  // 300000

// ---------------- device scratch (no allocations allowed) ----------------
__device__ int    g_cnt[NN];
__device__ float  g_dinv[NN];
__device__ int    g_rowptr[NN + 1];
__device__ int    g_cursor[NN];
__device__ int2   g_csr[NE];          // {src, norm bits}
__device__ int    g_tsum[NT];
__device__ int    g_toff[NT];
__device__ __half g_h[NN * NH];       // gemm1 output (x @ W1), fp16
__device__ float  g_z[NN];            // per-node scalar z = relu-row . (W2@Wl)
__device__ float  g_w64[NH];          // W2 @ Wl
__device__ float  g_b2wl;             // b2 . Wl
__device__ float  g_pool_s[NG];
__device__ int    g_gcnt[NG];

// ---------------- side stream + events (created once, before harness baseline) ----
struct ForkResources {
    cudaStream_t s2;
    cudaEvent_t evFork, evJoin;
    ForkResources() {
        cudaStreamCreateWithFlags(&s2, cudaStreamNonBlocking);
        cudaEventCreateWithFlags(&evFork, cudaEventDisableTiming);
        cudaEventCreateWithFlags(&evJoin, cudaEventDisableTiming);
    }
};
static ForkResources g_fork;

// ---------------- tf32 mma helpers ----------------
__device__ __forceinline__ unsigned tf32of(float f) {
    unsigned r;
    asm("cvt.rna.tf32.f32 %0, %1;" : "=r"(r) : "f"(f));
    return r;
}
__device__ __forceinline__ void mma_tf32(float* c,
                                         unsigned a0, unsigned a1,
                                         unsigned a2, unsigned a3,
                                         unsigned b0, unsigned b1) {
    asm("mma.sync.aligned.m16n8k8.row.col.f32.tf32.tf32.f32 "
        "{%0,%1,%2,%3}, {%4,%5,%6,%7}, {%8,%9}, {%0,%1,%2,%3};"
        : "+f"(c[0]), "+f"(c[1]), "+f"(c[2]), "+f"(c[3])
        : "r"(a0), "r"(a1), "r"(a2), "r"(a3), "r"(b0), "r"(b1));
}

// ---------------- degree count over dst (int4, 4 edges/thread) ----------------
__global__ void count_k(const int4* __restrict__ dst4) {
    int e = blockIdx.x * blockDim.x + threadIdx.x;
    if (e < NE4) {
        int4 d = __ldg(&dst4[e]);
        atomicAdd(&g_cnt[d.x], 1);
        atomicAdd(&g_cnt[d.y], 1);
        atomicAdd(&g_cnt[d.z], 1);
        atomicAdd(&g_cnt[d.w], 1);
    }
}

// ---------------- w = W2 @ Wl  (64 threads), b2wl ----------------
__global__ void w64_k(const float* __restrict__ W2,
                      const float* __restrict__ b2,
                      const float* __restrict__ Wl) {
    int i = threadIdx.x;
    if (i < NH) {
        float s = 0.f;
#pragma unroll
        for (int j = 0; j < NH; j++) s = fmaf(W2[i * NH + j], Wl[j], s);
        g_w64[i] = s;
    }
    if (i == 0) {
        float s = 0.f;
        for (int j = 0; j < NH; j++) s = fmaf(b2[j], Wl[j], s);
        g_b2wl = s;
    }
}

// ---------------- stage 1: per-tile sums + dinv (fused) ----------------
__global__ void tsum_k() {
    __shared__ int sm[TILE];
    int t = threadIdx.x;
    int i = blockIdx.x * TILE + t;
    int c = (i < NN) ? g_cnt[i] : 0;
    if (i < NN) g_dinv[i] = rsqrtf((float)(c + 1));  // +1 self loop
    sm[t] = c;
    __syncthreads();
#pragma unroll
    for (int off = TILE / 2; off > 0; off >>= 1) {
        if (t < off) sm[t] += sm[t + off];
        __syncthreads();
    }
    if (t == 0) g_tsum[blockIdx.x] = sm[0];
}

// ---------------- stage 2: scan tile sums ----------------
__global__ void toff_k() {
    __shared__ int sm[256];
    int t = threadIdx.x;
    int v = (t < NT) ? g_tsum[t] : 0;
    sm[t] = v;
    __syncthreads();
#pragma unroll
    for (int off = 1; off < 256; off <<= 1) {
        int u = (t >= off) ? sm[t - off] : 0;
        __syncthreads();
        sm[t] += u;
        __syncthreads();
    }
    if (t < NT) g_toff[t] = sm[t] - v;
    if (t == 255) g_rowptr[NN] = sm[255];
}

// ---------------- stage 3: per-tile exclusive scan -> rowptr & cursor ----------------
__global__ void tscan_k() {
    __shared__ int sm[TILE];
    int t = threadIdx.x;
    int i = blockIdx.x * TILE + t;
    int v = (i < NN) ? g_cnt[i] : 0;
    sm[t] = v;
    __syncthreads();
#pragma unroll
    for (int off = 1; off < TILE; off <<= 1) {
        int u = (t >= off) ? sm[t - off] : 0;
        __syncthreads();
        sm[t] += u;
        __syncthreads();
    }
    if (i < NN) {
        int pos = g_toff[blockIdx.x] + sm[t] - v;
        g_rowptr[i] = pos;
        g_cursor[i] = pos;
    }
}

// ---------------- scatter edges into CSR (int4, 4 edges/thread) ----------------
__global__ void scatter_k(const int4* __restrict__ src4,
                          const int4* __restrict__ dst4) {
    int e = blockIdx.x * blockDim.x + threadIdx.x;
    if (e >= NE4) return;
    int4 s = __ldg(&src4[e]);
    int4 d = __ldg(&dst4[e]);
    int p;
    p = atomicAdd(&g_cursor[d.x], 1);
    g_csr[p] = make_int2(s.x, __float_as_int(g_dinv[s.x] * g_dinv[d.x]));
    p = atomicAdd(&g_cursor[d.y], 1);
    g_csr[p] = make_int2(s.y, __float_as_int(g_dinv[s.y] * g_dinv[d.y]));
    p = atomicAdd(&g_cursor[d.z], 1);
    g_csr[p] = make_int2(s.z, __float_as_int(g_dinv[s.z] * g_dinv[d.z]));
    p = atomicAdd(&g_cursor[d.w], 1);
    g_csr[p] = make_int2(s.w, __float_as_int(g_dinv[s.w] * g_dinv[d.w]));
}

// ---------------- TF32 tensor GEMM: g_h[M x 64] = A[M x 128] @ W1[128 x 64], fp16 out ----
__global__ void gemm1_k(const float* __restrict__ A,
                        const float* __restrict__ W, int M) {
    __shared__ unsigned As[128][20];   // tf32 bits, [m][k], pad 4
    __shared__ unsigned Bs[16][68];    // tf32 bits, [k][n], pad 4

    int tid  = threadIdx.x;
    int lane = tid & 31, w = tid >> 5;
    int gid  = lane >> 2, tig = lane & 3;
    int rowBase = blockIdx.x * 128;

    float c[8][4];
#pragma unroll
    for (int nt = 0; nt < 8; nt++)
#pragma unroll
        for (int j = 0; j < 4; j++) c[nt][j] = 0.f;

    for (int k0 = 0; k0 < NF; k0 += 16) {
        {
            int r  = tid >> 1;
            int kq = (tid & 1) * 8;
            int row = rowBase + r;
            float4 a0 = make_float4(0, 0, 0, 0), a1 = a0;
            if (row < M) {
                const float* p = &A[(size_t)row * NF + k0 + kq];
                a0 = *(const float4*)p;
                a1 = *(const float4*)(p + 4);
            }
            As[r][kq + 0] = tf32of(a0.x); As[r][kq + 1] = tf32of(a0.y);
            As[r][kq + 2] = tf32of(a0.z); As[r][kq + 3] = tf32of(a0.w);
            As[r][kq + 4] = tf32of(a1.x); As[r][kq + 5] = tf32of(a1.y);
            As[r][kq + 6] = tf32of(a1.z); As[r][kq + 7] = tf32of(a1.w);
        }
        {
            int kr = tid >> 4;
            int nq = (tid & 15) * 4;
            float4 b = *(const float4*)&W[(size_t)(k0 + kr) * 64 + nq];
            Bs[kr][nq + 0] = tf32of(b.x); Bs[kr][nq + 1] = tf32of(b.y);
            Bs[kr][nq + 2] = tf32of(b.z); Bs[kr][nq + 3] = tf32of(b.w);
        }
        __syncthreads();
#pragma unroll
        for (int ks = 0; ks < 16; ks += 8) {
            unsigned a0 = As[w * 16 + gid    ][ks + tig    ];
            unsigned a1 = As[w * 16 + gid + 8][ks + tig    ];
            unsigned a2 = As[w * 16 + gid    ][ks + tig + 4];
            unsigned a3 = As[w * 16 + gid + 8][ks + tig + 4];
#pragma unroll
            for (int nt = 0; nt < 8; nt++) {
                unsigned b0 = Bs[ks + tig    ][nt * 8 + gid];
                unsigned b1 = Bs[ks + tig + 4][nt * 8 + gid];
                mma_tf32(c[nt], a0, a1, a2, a3, b0, b1);
            }
        }
        __syncthreads();
    }
    int r0 = rowBase + w * 16 + gid;
#pragma unroll
    for (int nt = 0; nt < 8; nt++) {
        int col = nt * 8 + 2 * tig;
        if (r0 < M) {
            __half2 h = __floats2half2_rn(c[nt][0], c[nt][1]);
            *(__half2*)&g_h[(size_t)r0 * 64 + col] = h;
        }
        if (r0 + 8 < M) {
            __half2 h = __floats2half2_rn(c[nt][2], c[nt][3]);
            *(__half2*)&g_h[(size_t)(r0 + 8) * 64 + col] = h;
        }
    }
}

// ---------------- gather1: 8 lanes per node, uint4 (8 halves) per lane ----------------
// acc = agg(g_h) + dinv^2 * h[node] + b1 ; relu ; z[node] = acc . w64
__global__ void gather1_k(const float* __restrict__ bias) {
    int node = (blockIdx.x * blockDim.x + threadIdx.x) >> 3;
    if (node >= NN) return;
    int g = threadIdx.x & 7;   // lane within 8-lane group; cols 8g..8g+7

    int beg = g_rowptr[node];
    int end = g_rowptr[node + 1];
    const uint4* __restrict__ h8 = (const uint4*)g_h;  // 8 halves per uint4

    float a0 = 0.f, a1 = 0.f, a2 = 0.f, a3 = 0.f;
    float a4 = 0.f, a5 = 0.f, a6 = 0.f, a7 = 0.f;
    int j = beg;
    for (; j + 2 <= end; j += 2) {
        int2 e0 = __ldg(&g_csr[j]);
        int2 e1 = __ldg(&g_csr[j + 1]);
        uint4 r0 = __ldg(&h8[(size_t)e0.x * 8 + g]);
        uint4 r1 = __ldg(&h8[(size_t)e1.x * 8 + g]);
        float n0 = __int_as_float(e0.y), n1 = __int_as_float(e1.y);
        float2 p;
        p = __half22float2(*(__half2*)&r0.x); a0 = fmaf(n0, p.x, a0); a1 = fmaf(n0, p.y, a1);
        p = __half22float2(*(__half2*)&r0.y); a2 = fmaf(n0, p.x, a2); a3 = fmaf(n0, p.y, a3);
        p = __half22float2(*(__half2*)&r0.z); a4 = fmaf(n0, p.x, a4); a5 = fmaf(n0, p.y, a5);
        p = __half22float2(*(__half2*)&r0.w); a6 = fmaf(n0, p.x, a6); a7 = fmaf(n0, p.y, a7);
        p = __half22float2(*(__half2*)&r1.x); a0 = fmaf(n1, p.x, a0); a1 = fmaf(n1, p.y, a1);
        p = __half22float2(*(__half2*)&r1.y); a2 = fmaf(n1, p.x, a2); a3 = fmaf(n1, p.y, a3);
        p = __half22float2(*(__half2*)&r1.z); a4 = fmaf(n1, p.x, a4); a5 = fmaf(n1, p.y, a5);
        p = __half22float2(*(__half2*)&r1.w); a6 = fmaf(n1, p.x, a6); a7 = fmaf(n1, p.y, a7);
    }
    if (j < end) {
        int2 e = __ldg(&g_csr[j]);
        uint4 r = __ldg(&h8[(size_t)e.x * 8 + g]);
        float n = __int_as_float(e.y);
        float2 p;
        p = __half22float2(*(__half2*)&r.x); a0 = fmaf(n, p.x, a0); a1 = fmaf(n, p.y, a1);
        p = __half22float2(*(__half2*)&r.y); a2 = fmaf(n, p.x, a2); a3 = fmaf(n, p.y, a3);
        p = __half22float2(*(__half2*)&r.z); a4 = fmaf(n, p.x, a4); a5 = fmaf(n, p.y, a5);
        p = __half22float2(*(__half2*)&r.w); a6 = fmaf(n, p.x, a6); a7 = fmaf(n, p.y, a7);
    }
    float di = g_dinv[node];
    float sn = di * di;
    uint4 rs = h8[(size_t)node * 8 + g];
    float4 bi0 = *(const float4*)&bias[8 * g];
    float4 bi1 = *(const float4*)&bias[8 * g + 4];
    float2 p;
    p = __half22float2(*(__half2*)&rs.x);
    a0 = fmaxf(fmaf(sn, p.x, a0) + bi0.x, 0.f);
    a1 = fmaxf(fmaf(sn, p.y, a1) + bi0.y, 0.f);
    p = __half22float2(*(__half2*)&rs.y);
    a2 = fmaxf(fmaf(sn, p.x, a2) + bi0.z, 0.f);
    a3 = fmaxf(fmaf(sn, p.y, a3) + bi0.w, 0.f);
    p = __half22float2(*(__half2*)&rs.z);
    a4 = fmaxf(fmaf(sn, p.x, a4) + bi1.x, 0.f);
    a5 = fmaxf(fmaf(sn, p.y, a5) + bi1.y, 0.f);
    p = __half22float2(*(__half2*)&rs.w);
    a6 = fmaxf(fmaf(sn, p.x, a6) + bi1.z, 0.f);
    a7 = fmaxf(fmaf(sn, p.y, a7) + bi1.w, 0.f);

    float4 w0 = *(const float4*)&g_w64[8 * g];
    float4 w1 = *(const float4*)&g_w64[8 * g + 4];
    float v = a0 * w0.x + a1 * w0.y + a2 * w0.z + a3 * w0.w
            + a4 * w1.x + a5 * w1.y + a6 * w1.z + a7 * w1.w;
#pragma unroll
    for (int o = 4; o; o >>= 1) v += __shfl_xor_sync(0xffffffffu, v, o);
    if (g == 0) g_z[node] = v;
}

// ---------------- gather2: thread per node, scalar agg + pool (4x unroll) ----------------
__global__ void gather2_k(const int* __restrict__ batch) {
    int node = blockIdx.x * blockDim.x + threadIdx.x;
    if (node >= NN) return;
    int beg = g_rowptr[node];
    int end = g_rowptr[node + 1];
    float s = 0.f;
    int j = beg;
    for (; j + 4 <= end; j += 4) {
        int2 e0 = __ldg(&g_csr[j]);
        int2 e1 = __ldg(&g_csr[j + 1]);
        int2 e2 = __ldg(&g_csr[j + 2]);
        int2 e3 = __ldg(&g_csr[j + 3]);
        float z0 = __ldg(&g_z[e0.x]);
        float z1 = __ldg(&g_z[e1.x]);
        float z2 = __ldg(&g_z[e2.x]);
        float z3 = __ldg(&g_z[e3.x]);
        s = fmaf(__int_as_float(e0.y), z0, s);
        s = fmaf(__int_as_float(e1.y), z1, s);
        s = fmaf(__int_as_float(e2.y), z2, s);
        s = fmaf(__int_as_float(e3.y), z3, s);
    }
    for (; j < end; j++) {
        int2 e = __ldg(&g_csr[j]);
        s = fmaf(__int_as_float(e.y), __ldg(&g_z[e.x]), s);
    }
    float di = g_dinv[node];
    s = fmaf(di * di, g_z[node], s);
    int g = batch[node];
    atomicAdd(&g_pool_s[g], s);
    atomicAdd(&g_gcnt[g], 1);
}

// ---------------- final ----------------
__global__ void final_k(const float* __restrict__ bl, float* __restrict__ out) {
    int g = blockIdx.x * blockDim.x + threadIdx.x;
    if (g >= NG) return;
    float c = (float)g_gcnt[g];
    out[g] = g_pool_s[g] / fmaxf(c, 1.f) + g_b2wl + bl[0];
}

// ---------------- launch ----------------
extern "C" void kernel_launch(void* const* d_in, const int* in_sizes, int n_in,
                              void* d_out, int out_size) {
    const float* x     = (const float*)d_in[0];
    const int*   ei    = (const int*)d_in[1];    // int32 (JAX x64 disabled)
    const int*   batch = (const int*)d_in[2];
    const float* W1    = (const float*)d_in[3];
    const float* b1    = (const float*)d_in[4];
    const float* W2    = (const float*)d_in[5];
    const float* b2    = (const float*)d_in[6];
    const float* Wl    = (const float*)d_in[7];
    const float* bl    = (const float*)d_in[8];
    float* out = (float*)d_out;

    const int4* src4 = (const int4*)ei;
    const int4* dst4 = (const int4*)(ei + NE);

    // zero-init via memset nodes (DMA, cheap)
    void *pCnt, *pPool, *pGcnt;
    cudaGetSymbolAddress(&pCnt, g_cnt);
    cudaGetSymbolAddress(&pPool, g_pool_s);
    cudaGetSymbolAddress(&pGcnt, g_gcnt);
    cudaMemsetAsync(pCnt, 0, NN * sizeof(int), 0);
    cudaMemsetAsync(pPool, 0, NG * sizeof(float), 0);
    cudaMemsetAsync(pGcnt, 0, NG * sizeof(int), 0);

    // ---- fork: GEMM branch on side stream (independent of CSR build) ----
    cudaEventRecord(g_fork.evFork, 0);
    cudaStreamWaitEvent(g_fork.s2, g_fork.evFork, 0);
    gemm1_k<<<(NN + 127) / 128, 256, 0, g_fork.s2>>>(x, W1, NN);
    w64_k  <<<1, 64, 0, g_fork.s2>>>(W2, b2, Wl);
    cudaEventRecord(g_fork.evJoin, g_fork.s2);

    // ---- main chain: CSR build on capture stream ----
    count_k  <<<(NE4 + 255) / 256, 256>>>(dst4);
    tsum_k   <<<NT, TILE>>>();
    toff_k   <<<1, 256>>>();
    tscan_k  <<<NT, TILE>>>();
    scatter_k<<<(NE4 + 255) / 256, 256>>>(src4, dst4);

    // ---- join: gathers need both CSR and g_h ----
    cudaStreamWaitEvent(0, g_fork.evJoin, 0);
    gather1_k<<<(NN * 8 + 255) / 256, 256>>>(b1);
    gather2_k<<<(NN + 255) / 256, 256>>>(batch);
    final_k  <<<1, NG>>>(bl, out);
}